// round 17
// baseline (speedup 1.0000x reference)
#include <cuda_runtime.h>

#define NV 1497600          // 256 * 5850
#define NE 4492800          // 3 * NV
#define NEH (NE/2)          // edge pairs
#define NB 256
#define VPM 5850
#define KDIM 58500          // VPM * 10
#define NEG 0.01f

// ---------------- scratch (static device memory; no allocs) ----------------
__device__ float g_p4[(size_t)NV * 4];    // (vx, vy, vz, 1)
__device__ float g_s1[(size_t)NV * 4];    // pass-1 scatter acc (w = degree)
__device__ float g_s28[(size_t)NV * 8];   // pass-2 scatter acc, stride 8
__device__ float g_y [(size_t)NV * 10];   // fc1 output == flat (256, 58500)
__device__ float g_logits[NB * 64];

__device__ __forceinline__ float leaky(float t) { return t >= 0.f ? t : NEG * t; }

__device__ __forceinline__ void red4(float* p, float4 v) {
    asm volatile("red.global.add.v4.f32 [%0], {%1,%2,%3,%4};"
                 :: "l"(p), "f"(v.x), "f"(v.y), "f"(v.z), "f"(v.w) : "memory");
}
__device__ __forceinline__ void red1(float* p, float v) {
    asm volatile("red.global.add.f32 [%0], %1;" :: "l"(p), "f"(v) : "memory");
}

// ---------- packed f32x2 helpers (FFMA2 — only reachable via PTX) ----------
typedef unsigned long long ull;
__device__ __forceinline__ ull pk2(float lo, float hi) {
    ull r; asm("mov.b64 %0, {%1, %2};" : "=l"(r) : "f"(lo), "f"(hi)); return r;
}
__device__ __forceinline__ void upk2(ull v, float& lo, float& hi) {
    asm("mov.b64 {%0, %1}, %2;" : "=f"(lo), "=f"(hi) : "l"(v));
}
__device__ __forceinline__ ull ffma2(ull a, ull b, ull c) {
    ull d; asm("fma.rn.f32x2 %0, %1, %2, %3;" : "=l"(d) : "l"(a), "l"(b), "l"(c)); return d;
}

// fill shared 5x8 layer-A row table: (w0[c][0..2], b0[c], w1[c][0..2], b1[c])
__device__ __forceinline__ void fill_wrowA(float (*wrow)[8], int t,
                                           const float* w0, const float* b0,
                                           const float* w1, const float* b1) {
    if (t < 40) {
        int c = t >> 3, k = t & 7;
        float val;
        if (k < 3)       val = w0[c*3 + k];
        else if (k == 3) val = b0[c];
        else if (k < 7)  val = w1[c*3 + (k - 4)];
        else             val = b1[c];
        wrow[c][k] = val;
    }
}

// xA'[c] = leaky( (p.xyz,1,s.xyz,s.w) . wrow[c] )
__device__ __forceinline__ float rowA(const float* r, float4 p, float4 s) {
    float a = fmaf(r[0], p.x, fmaf(r[1], p.y, fmaf(r[2], p.z, r[3])));
    a = fmaf(r[4], s.x, fmaf(r[5], s.y, fmaf(r[6], s.z, fmaf(r[7], s.w, a))));
    return leaky(a);
}

// ---------------- K1: pack verts -> p4, zero s1/s28/logits ----------------
__global__ void k1_pack(const float* __restrict__ verts) {
    int v = blockIdx.x * blockDim.x + threadIdx.x;
    if (v >= NV) return;
    float p0 = verts[(size_t)v*3+0], p1 = verts[(size_t)v*3+1], p2 = verts[(size_t)v*3+2];
    float4 z = make_float4(0.f, 0.f, 0.f, 0.f);
    *(float4*)&g_p4[(size_t)v*4] = make_float4(p0, p1, p2, 1.0f);
    *(float4*)&g_s1[(size_t)v*4] = z;
    *(float4*)&g_s28[(size_t)v*8]     = z;
    *(float4*)&g_s28[(size_t)v*8 + 4] = z;
    if (v < NB * 64) g_logits[v] = 0.f;
}

// -------- K2: pass-1 scatter (raw verts + degree), 2 edges/thread --------
__global__ void k2_scatter1(const int* __restrict__ edges) {
    int e = blockIdx.x * blockDim.x + threadIdx.x;
    if (e >= NEH) return;
    int4 q = __ldcs(&((const int4*)edges)[e]);
    float4 a = *(const float4*)&g_p4[(size_t)q.y * 4];
    float4 b = *(const float4*)&g_p4[(size_t)q.x * 4];
    float4 c = *(const float4*)&g_p4[(size_t)q.w * 4];
    float4 d = *(const float4*)&g_p4[(size_t)q.z * 4];
    red4(&g_s1[(size_t)q.x * 4], a);
    red4(&g_s1[(size_t)q.y * 4], b);
    red4(&g_s1[(size_t)q.z * 4], c);
    red4(&g_s1[(size_t)q.w * 4], d);
}

// ---- K4: pass-2 scatter, fused layer-A recompute. 2 edges/thread. ----
__global__ void __launch_bounds__(256)
k4_scatter2(const int* __restrict__ edges,
            const float* __restrict__ w0, const float* __restrict__ b0,
            const float* __restrict__ w1, const float* __restrict__ b1) {
    __shared__ float wrow[5][8];
    int t = threadIdx.x;
    fill_wrowA(wrow, t, w0, b0, w1, b1);
    __syncthreads();
    int e = blockIdx.x * blockDim.x + t;
    if (e >= NEH) return;
    int4 q = __ldcs(&((const int4*)edges)[e]);
    // issue all 8 gathers up front (MLP=8)
    float4 pi = *(const float4*)&g_p4[(size_t)q.x * 4];
    float4 pj = *(const float4*)&g_p4[(size_t)q.y * 4];
    float4 pk = *(const float4*)&g_p4[(size_t)q.z * 4];
    float4 pl = *(const float4*)&g_p4[(size_t)q.w * 4];
    float4 si = *(const float4*)&g_s1[(size_t)q.x * 4];
    float4 sj = *(const float4*)&g_s1[(size_t)q.y * 4];
    float4 sk = *(const float4*)&g_s1[(size_t)q.z * 4];
    float4 sl = *(const float4*)&g_s1[(size_t)q.w * 4];
    float qi[5], qj[5], qk[5], ql[5];
#pragma unroll
    for (int c = 0; c < 5; c++) {
        float r[8];
#pragma unroll
        for (int k = 0; k < 8; k++) r[k] = wrow[c][k];
        qi[c] = rowA(r, pi, si);
        qj[c] = rowA(r, pj, sj);
        qk[c] = rowA(r, pk, sk);
        ql[c] = rowA(r, pl, sl);
    }
    size_t oi = (size_t)q.x * 8, oj = (size_t)q.y * 8;
    size_t ok = (size_t)q.z * 8, ol = (size_t)q.w * 8;
    red4(&g_s28[oi], make_float4(qj[0], qj[1], qj[2], qj[3]));  red1(&g_s28[oi + 4], qj[4]);
    red4(&g_s28[oj], make_float4(qi[0], qi[1], qi[2], qi[3]));  red1(&g_s28[oj + 4], qi[4]);
    red4(&g_s28[ok], make_float4(ql[0], ql[1], ql[2], ql[3]));  red1(&g_s28[ok + 4], ql[4]);
    red4(&g_s28[ol], make_float4(qk[0], qk[1], qk[2], qk[3]));  red1(&g_s28[ol + 4], qk[4]);
}

// ---- K5 (FFMA2): recompute x=leaky(linA); xB=leaky(linB); y=leaky(fc1) ----
__global__ void k5_fused(const float* __restrict__ wa0, const float* __restrict__ ba0,
                         const float* __restrict__ wa1, const float* __restrict__ ba1,
                         const float* __restrict__ w0, const float* __restrict__ b0,
                         const float* __restrict__ w1, const float* __restrict__ b1,
                         const float* __restrict__ fw, const float* __restrict__ fb) {
    __shared__ float wrow[5][8];
    __shared__ ull sw0p[50], sw1p[50];   // [c*10 + p], pair p = (2p, 2p+1) of 20 outputs
    __shared__ ull sfwp[100];            // [c*5 + p],  pair p of 10 outputs
    __shared__ ull sb0p[10], sb1p[10], sfbp[5];
    int t = threadIdx.x;
    fill_wrowA(wrow, t, wa0, ba0, wa1, ba1);
    if (t < 50) {
        int c = t / 10, p = t % 10;
        sw0p[t] = pk2(w0[(2*p)*5 + c], w0[(2*p+1)*5 + c]);
        sw1p[t] = pk2(w1[(2*p)*5 + c], w1[(2*p+1)*5 + c]);
    }
    if (t < 100) {
        int c = t / 5, p = t % 5;
        sfwp[t] = pk2(fw[(2*p)*20 + c], fw[(2*p+1)*20 + c]);
    }
    if (t < 10) { sb0p[t] = pk2(b0[2*t], b0[2*t+1]); sb1p[t] = pk2(b1[2*t], b1[2*t+1]); }
    if (t < 5)  { sfbp[t] = pk2(fb[2*t], fb[2*t+1]); }
    __syncthreads();
    int v = blockIdx.x * blockDim.x + t;
    if (v >= NV) return;
    float4 p = *(const float4*)&g_p4[(size_t)v*4];
    float4 s1v = *(const float4*)&g_s1[(size_t)v*4];
    float4 sq = *(const float4*)&g_s28[(size_t)v*8];
    float  s4 = g_s28[(size_t)v*8 + 4];
    float x[5];
#pragma unroll
    for (int c = 0; c < 5; c++) x[c] = rowA(wrow[c], p, s1v);
    float s[5] = {sq.x, sq.y, sq.z, sq.w, s4};
    float deg = s1v.w;

    ull degd = pk2(deg, deg);
    ull xbp[10];
#pragma unroll
    for (int pp = 0; pp < 10; pp++) xbp[pp] = ffma2(degd, sb1p[pp], sb0p[pp]);
#pragma unroll
    for (int c = 0; c < 5; c++) {
        ull xc = pk2(x[c], x[c]);
        ull sc = pk2(s[c], s[c]);
#pragma unroll
        for (int pp = 0; pp < 10; pp++)
            xbp[pp] = ffma2(xc, sw0p[c*10 + pp], ffma2(sc, sw1p[c*10 + pp], xbp[pp]));
    }
    ull hp[5];
#pragma unroll
    for (int pp = 0; pp < 5; pp++) hp[pp] = sfbp[pp];
#pragma unroll
    for (int c2 = 0; c2 < 10; c2++) {
        float lo, hi; upk2(xbp[c2], lo, hi);
        lo = leaky(lo); hi = leaky(hi);
        ull xa = pk2(lo, lo), xb_ = pk2(hi, hi);
#pragma unroll
        for (int pp = 0; pp < 5; pp++)
            hp[pp] = ffma2(xa, sfwp[(2*c2)*5 + pp], ffma2(xb_, sfwp[(2*c2+1)*5 + pp], hp[pp]));
    }
#pragma unroll
    for (int pp = 0; pp < 5; pp++) {
        float lo, hi; upk2(hp[pp], lo, hi);
        *(float2*)&g_y[(size_t)v*10 + 2*pp] = make_float2(leaky(lo), leaky(hi));
    }
}

// ------- K6: split-K GEMM with FFMA2. BM=256 (whole M), BN=64. ----------
// KDIM = 58500 = 325 * 180; KSPLIT=180, BK=20 — no bounds checks needed.
#define K6_BK 20
#define K6_KSPLIT 180
__global__ void __launch_bounds__(256, 2)
k6_gemm(const float* __restrict__ w) {
    __shared__ float Ys[256][K6_BK + 1];   // [m][k]
    __shared__ float Wsk[K6_BK][66];       // [k][n] -> n-pairs contiguous for 8B loads
    int t = threadIdx.x;                   // 256 threads
    int kbase = blockIdx.x * K6_KSPLIT;
    int tr = t & 31;                       // m sub-index (lane)
    int tc = t >> 5;                       // warp id: n block of 8
    ull acc[8][4] = {};                    // 8 m x 4 n-pairs, packed f32x2
    for (int kk = 0; kk < K6_KSPLIT; kk += K6_BK) {
        // Y tile: 256 rows x 20 k = 1280 float4, 5 per thread
#pragma unroll
        for (int r = 0; r < 5; r++) {
            int idx = t + r * 256;
            int row = idx / 5;
            int kc  = (idx % 5) * 4;
            float4 yv = __ldcs((const float4*)&g_y[(size_t)row * KDIM + kbase + kk + kc]);
            Ys[row][kc+0] = yv.x; Ys[row][kc+1] = yv.y;
            Ys[row][kc+2] = yv.z; Ys[row][kc+3] = yv.w;
        }
        // W tile: 64 rows x 20 k = 320 float4, transposed into [k][n]
#pragma unroll
        for (int r = 0; r < 2; r++) {
            int idx = t + r * 256;
            if (idx < 320) {
                int n  = idx / 5;
                int kc = (idx % 5) * 4;
                float4 wv = __ldcs((const float4*)&w[(size_t)n * KDIM + kbase + kk + kc]);
                Wsk[kc+0][n] = wv.x; Wsk[kc+1][n] = wv.y;
                Wsk[kc+2][n] = wv.z; Wsk[kc+3][n] = wv.w;
            }
        }
        __syncthreads();
#pragma unroll 5
        for (int k2 = 0; k2 < K6_BK; k2++) {
            ull ya2[8];
#pragma unroll
            for (int u = 0; u < 8; u++) {
                float y = Ys[tr + 32*u][k2];
                ya2[u] = pk2(y, y);
            }
            ull wv[4];
#pragma unroll
            for (int v2 = 0; v2 < 4; v2++)
                wv[v2] = *(const ull*)&Wsk[k2][tc*8 + 2*v2];   // warp-uniform broadcast
#pragma unroll
            for (int u = 0; u < 8; u++)
#pragma unroll
                for (int v2 = 0; v2 < 4; v2++)
                    acc[u][v2] = ffma2(ya2[u], wv[v2], acc[u][v2]);
        }
        __syncthreads();
    }
#pragma unroll
    for (int u = 0; u < 8; u++) {
        int row = tr + 32*u;
        float a, b, c, d;
        upk2(acc[u][0], a, b); upk2(acc[u][1], c, d);
        red4(&g_logits[row*64 + tc*8], make_float4(a, b, c, d));
        upk2(acc[u][2], a, b); upk2(acc[u][3], c, d);
        red4(&g_logits[row*64 + tc*8 + 4], make_float4(a, b, c, d));
    }
}

// ---------------- K7: bias + softmax(64) ----------------
__global__ void k7_softmax(const float* __restrict__ fb, float* __restrict__ out) {
    int b = blockIdx.x;
    int t = threadIdx.x;   // 64 threads
    float v = g_logits[b * 64 + t] + fb[t];
    __shared__ float r0[2], r1[2];
    float m = v;
#pragma unroll
    for (int o = 16; o; o >>= 1) m = fmaxf(m, __shfl_xor_sync(0xffffffffu, m, o));
    if ((t & 31) == 0) r0[t >> 5] = m;
    __syncthreads();
    m = fmaxf(r0[0], r0[1]);
    float e = expf(v - m);
    float s = e;
#pragma unroll
    for (int o = 16; o; o >>= 1) s += __shfl_xor_sync(0xffffffffu, s, o);
    if ((t & 31) == 0) r1[t >> 5] = s;
    __syncthreads();
    s = r1[0] + r1[1];
    out[b * 64 + t] = e / s;
}

// ---------------- launch ----------------
extern "C" void kernel_launch(void* const* d_in, const int* in_sizes, int n_in,
                              void* d_out, int out_size) {
    const float* verts = (const float*)d_in[0];
    const int*   edges = (const int*)  d_in[1];
    const float* w0a = (const float*)d_in[2];  const float* b0a = (const float*)d_in[3];
    const float* w1a = (const float*)d_in[4];  const float* b1a = (const float*)d_in[5];
    const float* w0b = (const float*)d_in[6];  const float* b0b = (const float*)d_in[7];
    const float* w1b = (const float*)d_in[8];  const float* b1b = (const float*)d_in[9];
    const float* f1w = (const float*)d_in[10]; const float* f1b = (const float*)d_in[11];
    const float* f2w = (const float*)d_in[12]; const float* f2b = (const float*)d_in[13];
    float* out = (float*)d_out;

    k1_pack    <<<(NV + 255) / 256, 256>>>(verts);
    k2_scatter1<<<(NEH + 255) / 256, 256>>>(edges);
    k4_scatter2<<<(NEH + 255) / 256, 256>>>(edges, w0a, b0a, w1a, b1a);
    k5_fused   <<<(NV + 255) / 256, 256>>>(w0a, b0a, w1a, b1a,
                                           w0b, b0b, w1b, b1b, f1w, f1b);
    k6_gemm    <<<KDIM / K6_KSPLIT, 256>>>(f2w);   // 325 blocks
    k7_softmax <<<NB, 64>>>(f2b, out);
}